// round 14
// baseline (speedup 1.0000x reference)
#include <cuda_runtime.h>
#include <cuda_bf16.h>
#include <cuda_fp16.h>
#include <math_constants.h>
#include <cstdint>

// Problem dims (fixed by setup_inputs)
constexpr int NP = 32768;   // 8*4096 points
constexpr int KC = 2048;    // codebook size
constexpr int D  = 128;     // dim
constexpr float LEPS = 1e-6f;
constexpr float OFFS = 128.0f;
constexpr float SCALE = 1.4426950408889634f / 0.9f;   // log2(e)/T
constexpr float RESCUE_THR_S = 0.5f * SCALE;          // raw 0.5 margin, scaled

// Fused kernel geometry
constexpr int MB = 32;                 // rows per block
constexpr int SC_STRIDE_H = 2056;      // 2048 + 8 pad halves -> 4112 B/row
constexpr int SC_OFF  = 0;                              // 32*4112 = 131584
constexpr int A_OFF   = 131584;                         // 2 x 32 x 128B = 8192
constexpr int E_OFF   = 139776;                         // 4 x 16384 = 65536
constexpr int ESQ_OFF = 205312;                         // 2048 floats = 8192
constexpr int FUSED_SMEM = 213504;

// Scratch (__device__ globals; no allocation allowed)
__device__ float g_esq[KC];                            // ||e_k||^2 (rescue)
__device__ float g_esqc[KC];                           // (OFFS - esq) * SCALE
__device__ __nv_bfloat16 g_Xs[(size_t)NP * 128];       // bf16(x)
__device__ __nv_bfloat16 g_Es[(size_t)KC * 256];       // 2-way bf16 split of embed
__device__ float g_part[(size_t)(NP / 32) * KC];       // per-block class partials
__device__ float g_part2[16 * KC];
__device__ float g_acc[KC];

// ---------------------------------------------------------------------------
__device__ __forceinline__ uint32_t smem_u32(const void* p) {
    uint32_t a;
    asm("{ .reg .u64 t; cvta.to.shared.u64 t, %1; cvt.u32.u64 %0, t; }" : "=r"(a) : "l"(p));
    return a;
}
__device__ __forceinline__ uint32_t sw128(uint32_t off) { return off ^ ((off >> 3) & 0x70); }
__device__ __forceinline__ float ex2f(float x) {
    float r;
    asm("ex2.approx.f32 %0, %1;" : "=f"(r) : "f"(x));
    return r;
}
__device__ __forceinline__ void cp_async16(uint32_t saddr, const void* gaddr) {
    asm volatile("cp.async.cg.shared.global [%0], [%1], 16;" :: "r"(saddr), "l"(gaddr));
}
#define CP_COMMIT() asm volatile("cp.async.commit_group;" ::: "memory")
#define CP_WAIT(n)  asm volatile("cp.async.wait_group %0;" :: "n"(n) : "memory")

__device__ __forceinline__ void ldm_x4(uint32_t* a, uint32_t addr) {
    asm volatile("ldmatrix.sync.aligned.m8n8.x4.shared.b16 {%0,%1,%2,%3}, [%4];"
                 : "=r"(a[0]), "=r"(a[1]), "=r"(a[2]), "=r"(a[3]) : "r"(addr));
}
__device__ __forceinline__ void mma_bf16(float* c, const uint32_t* a, const uint32_t* b) {
    asm volatile("mma.sync.aligned.m16n8k16.row.col.f32.bf16.bf16.f32 "
                 "{%0,%1,%2,%3}, {%4,%5,%6,%7}, {%8,%9}, {%0,%1,%2,%3};"
                 : "+f"(c[0]), "+f"(c[1]), "+f"(c[2]), "+f"(c[3])
                 : "r"(a[0]), "r"(a[1]), "r"(a[2]), "r"(a[3]), "r"(b[0]), "r"(b[1]));
}

// ---------------------------------------------------------------------------
// Kernel 0: bf16 conversion of x; 2-way bf16 split of embed
// ---------------------------------------------------------------------------
__global__ __launch_bounds__(256) void split_kernel(const float* __restrict__ x,
                                                    const float* __restrict__ e) {
    int i = blockIdx.x * 256 + threadIdx.x;
    if (i < NP * D) {
        g_Xs[i] = __float2bfloat16(x[i]);
    } else {
        int j = i - NP * D;
        if (j >= KC * D) return;
        float v = e[j];
        int c = j & (D - 1);
        __nv_bfloat16* dst = g_Es + (size_t)(j >> 7) * 256;
        __nv_bfloat16 b0 = __float2bfloat16(v);
        float r1 = v - __bfloat162float(b0);
        __nv_bfloat16 b1 = __float2bfloat16(r1);
        dst[c] = b0; dst[128 + c] = b1;
    }
}

// ---------------------------------------------------------------------------
// Kernel 1: e_sq (exact) + scaled epilogue constant
// ---------------------------------------------------------------------------
__global__ void prep_kernel(const float* __restrict__ embed) {
    int k = blockIdx.x * blockDim.x + threadIdx.x;
    if (k < KC) {
        const float4* e = (const float4*)(embed + (size_t)k * D);
        float s = 0.f;
#pragma unroll
        for (int i = 0; i < D / 4; i++) {
            float4 v = e[i];
            s += v.x * v.x + v.y * v.y + v.z * v.z + v.w * v.w;
        }
        g_esq[k] = s;
        g_esqc[k] = (OFFS - s) * SCALE;
    }
}

// ---------------------------------------------------------------------------
// Kernel 2 (FUSED): per 32-row block — mma scores into SMEM (fp16, scaled),
// then argmax + exact rescue + softmax + class bins, all without touching
// a global score matrix.
// 512 thr (16 warps). Warp tile 16x16. E streamed in 16KB chunks, ring of 4.
// Chunk ci: t = ci>>2 (N-tile of 128 codes), p = (ci>>1)&1 (e0/e1), h = ci&1.
// ---------------------------------------------------------------------------
__global__ __launch_bounds__(512, 1) void fused_kernel(const float* __restrict__ x,
                                                       const float* __restrict__ embed,
                                                       float* __restrict__ out) {
    extern __shared__ __align__(128) char smem[];
    const uint32_t sb = smem_u32(smem);
    __shared__ int s_cnt[16];
    __shared__ int s_list[16][32];

    const int tid = threadIdx.x, wid = tid >> 5, lane = tid & 31;
    const int warp_m = wid & 1, warp_n = wid >> 1;     // 2 x 8 warp grid
    const int row0 = blockIdx.x * MB;

    // ---- prologue loads ----
    // esqc -> smem (512 thr x 1 float4)
    {
        float4 v = *(const float4*)(g_esqc + tid * 4);
        *(float4*)(smem + ESQ_OFF + tid * 16) = v;
    }
    // A tile: 2 halves x 32 rows x 8 segs of 16B; 1 seg per thread
    {
        const int h = tid >> 8, idx = tid & 255;
        const int row = idx >> 3, seg = idx & 7;
        cp_async16(sb + A_OFF + h * 4096 + sw128((uint32_t)row * 128 + seg * 16),
                   g_Xs + (size_t)(row0 + row) * 128 + h * 64 + seg * 8);
    }
    // E chunk loader: 128 rows x 8 segs = 1024 segs; 2 per thread
    const int e_lr = tid >> 2;            // 0..127
    const int e_ls = (tid & 3) * 2;       // seg base
    auto issue_chunk = [&](int ci) {
        const int stage = ci & 3, t = ci >> 2, p = (ci >> 1) & 1, h = ci & 1;
        const uint32_t es = sb + E_OFF + stage * 16384;
        const __nv_bfloat16* gb = g_Es + (size_t)(t * 128 + e_lr) * 256 + p * 128 + h * 64;
#pragma unroll
        for (int s = 0; s < 2; s++)
            cp_async16(es + sw128((uint32_t)e_lr * 128 + (e_ls + s) * 16),
                       gb + (e_ls + s) * 8);
        CP_COMMIT();
    };
    issue_chunk(0);     // group 0 also carries the A tile
    issue_chunk(1);
    issue_chunk(2);

    // ldmatrix lane components (same pattern as verified GEMM, warp tile 16x16)
    const int arow = warp_m * 16 + (lane & 7) + ((lane >> 3) & 1) * 8;
    const int acol = ((lane >> 4) & 1) * 16;
    const int b_lrow = ((lane >> 4) & 1) * 8 + (lane & 7);
    const int b_lcol = ((lane >> 3) & 1) * 16;

    float acc[2][4];
#pragma unroll
    for (int nt = 0; nt < 2; nt++)
#pragma unroll
        for (int q = 0; q < 4; q++) acc[nt][q] = 0.f;

    // ---- mma mainloop: 64 chunks ----
#pragma unroll 1
    for (int ci = 0; ci < 64; ci++) {
        if (ci < 62) { CP_WAIT(2); } else if (ci == 62) { CP_WAIT(1); } else { CP_WAIT(0); }
        __syncthreads();

        const int stage = ci & 3, t = ci >> 2, h = ci & 1;
        const uint32_t abase = sb + A_OFF + h * 4096;
        const uint32_t ebase = sb + E_OFF + stage * 16384;
#pragma unroll
        for (int ks = 0; ks < 4; ks++) {
            uint32_t a[4], b[4];
            ldm_x4(a, abase + sw128((uint32_t)arow * 128 + ks * 32 + acol));
            ldm_x4(b, ebase + sw128((uint32_t)(warp_n * 16 + b_lrow) * 128 + ks * 32 + b_lcol));
            mma_bf16(acc[0], a, b);
            mma_bf16(acc[1], a, b + 2);
        }

        if ((ci & 3) == 3) {
            // tile t complete: write scaled fp16 scores into smem (conflict-free)
            const int r = warp_m * 16 + (lane >> 2);
#pragma unroll
            for (int nt = 0; nt < 2; nt++) {
                const int c0 = t * 128 + warp_n * 16 + nt * 8 + 2 * (lane & 3);
                const float2 eq = *(const float2*)(smem + ESQ_OFF + c0 * 4);
                const float v0 = fmaf(acc[nt][0], 2.f * SCALE, eq.x);
                const float v1 = fmaf(acc[nt][1], 2.f * SCALE, eq.y);
                const float v2 = fmaf(acc[nt][2], 2.f * SCALE, eq.x);
                const float v3 = fmaf(acc[nt][3], 2.f * SCALE, eq.y);
                *(__half2*)(smem + SC_OFF + (size_t)r * (SC_STRIDE_H * 2) + c0 * 2) =
                    __floats2half2_rn(v0, v1);
                *(__half2*)(smem + SC_OFF + (size_t)(r + 8) * (SC_STRIDE_H * 2) + c0 * 2) =
                    __floats2half2_rn(v2, v3);
                acc[nt][0] = acc[nt][1] = acc[nt][2] = acc[nt][3] = 0.f;
            }
        }
        if (ci < 61) issue_chunk(ci + 3);
    }
    __syncthreads();

    // ---- row phase ----
    // cpb overlays the (dead) E ring: 2 arrays of 2048 floats
    float* cpb = (float*)(smem + E_OFF);
    for (int i = tid; i < 2 * KC; i += 512) cpb[i] = 0.f;
    __syncthreads();

    float bins[64];
#pragma unroll
    for (int j = 0; j < 64; j++) bins[j] = 0.f;

    for (int rr = 0; rr < 2; rr++) {
        const int row = wid * 2 + rr;
        const int grow = row0 + row;
        uint4* srow = (uint4*)(smem + SC_OFF + (size_t)row * (SC_STRIDE_H * 2));

        // pass 1: max + argmax
        float m = -CUDART_INF_F;
        int mi = 0;
#pragma unroll
        for (int j = 0; j < 8; j++) {
            const uint4 qq = srow[j * 32 + lane];
            const float2 f0 = __half22float2(*(const __half2*)&qq.x);
            const float2 f1 = __half22float2(*(const __half2*)&qq.y);
            const float2 f2 = __half22float2(*(const __half2*)&qq.z);
            const float2 f3 = __half22float2(*(const __half2*)&qq.w);
            const int kbase = j * 256 + lane * 8;
            if (f0.x > m) { m = f0.x; mi = kbase; }
            if (f0.y > m) { m = f0.y; mi = kbase + 1; }
            if (f1.x > m) { m = f1.x; mi = kbase + 2; }
            if (f1.y > m) { m = f1.y; mi = kbase + 3; }
            if (f2.x > m) { m = f2.x; mi = kbase + 4; }
            if (f2.y > m) { m = f2.y; mi = kbase + 5; }
            if (f3.x > m) { m = f3.x; mi = kbase + 6; }
            if (f3.y > m) { m = f3.y; mi = kbase + 7; }
        }
#pragma unroll
        for (int off = 16; off > 0; off >>= 1) {
            float om = __shfl_xor_sync(0xffffffffu, m, off);
            int oi = __shfl_xor_sync(0xffffffffu, mi, off);
            if (om > m || (om == m && oi < mi)) { m = om; mi = oi; }
        }

        // pass 2: exp, sum, candidate push, write exps back over scores
        if (lane == 0) s_cnt[wid] = 0;
        __syncwarp();
        const float thr = m - RESCUE_THR_S;
        float s = 0.f;
#pragma unroll
        for (int j = 0; j < 8; j++) {
            uint4 qq = srow[j * 32 + lane];
            const float2 f0 = __half22float2(*(const __half2*)&qq.x);
            const float2 f1 = __half22float2(*(const __half2*)&qq.y);
            const float2 f2 = __half22float2(*(const __half2*)&qq.z);
            const float2 f3 = __half22float2(*(const __half2*)&qq.w);
            float fv[8] = {f0.x, f0.y, f1.x, f1.y, f2.x, f2.y, f3.x, f3.y};
            float ev[8];
#pragma unroll
            for (int q = 0; q < 8; q++) {
                ev[q] = ex2f(fv[q] - m);
                s += ev[q];
                if (fv[q] > thr) {
                    int pos = atomicAdd(&s_cnt[wid], 1);
                    if (pos < 32) s_list[wid][pos] = j * 256 + lane * 8 + q;
                }
            }
            __half2 h0 = __floats2half2_rn(ev[0], ev[1]);
            __half2 h1 = __floats2half2_rn(ev[2], ev[3]);
            __half2 h2 = __floats2half2_rn(ev[4], ev[5]);
            __half2 h3 = __floats2half2_rn(ev[6], ev[7]);
            qq.x = *(const uint32_t*)&h0; qq.y = *(const uint32_t*)&h1;
            qq.z = *(const uint32_t*)&h2; qq.w = *(const uint32_t*)&h3;
            srow[j * 32 + lane] = qq;
        }
        __syncwarp();
#pragma unroll
        for (int off = 16; off > 0; off >>= 1)
            s += __shfl_xor_sync(0xffffffffu, s, off);

        // exact fp32 rescue for near-ties (deterministic)
        const int cnt = s_cnt[wid];
        if (cnt > 1) {
            const int nc = min(cnt, 32);
            const float4 xa = *(const float4*)(x + (size_t)grow * D + lane * 4);
            float bv = -CUDART_INF_F; int bi = 0x7fffffff;
            for (int tt = 0; tt < nc; tt++) {
                const int cidx = s_list[wid][tt];
                const float4 ea = *(const float4*)(embed + (size_t)cidx * D + lane * 4);
                float d = xa.x * ea.x + xa.y * ea.y + xa.z * ea.z + xa.w * ea.w;
#pragma unroll
                for (int off = 16; off > 0; off >>= 1)
                    d += __shfl_xor_sync(0xffffffffu, d, off);
                const float sc = 2.f * d - g_esq[cidx];
                if (sc > bv || (sc == bv && cidx < bi)) { bv = sc; bi = cidx; }
            }
            mi = bi;
        }

        // pass 3: bins += e * inv
        const float inv = 1.f / s;
#pragma unroll
        for (int j = 0; j < 8; j++) {
            const uint4 qq = srow[j * 32 + lane];
            const float2 f0 = __half22float2(*(const __half2*)&qq.x);
            const float2 f1 = __half22float2(*(const __half2*)&qq.y);
            const float2 f2 = __half22float2(*(const __half2*)&qq.z);
            const float2 f3 = __half22float2(*(const __half2*)&qq.w);
            bins[8 * j + 0] = fmaf(f0.x, inv, bins[8 * j + 0]);
            bins[8 * j + 1] = fmaf(f0.y, inv, bins[8 * j + 1]);
            bins[8 * j + 2] = fmaf(f1.x, inv, bins[8 * j + 2]);
            bins[8 * j + 3] = fmaf(f1.y, inv, bins[8 * j + 3]);
            bins[8 * j + 4] = fmaf(f2.x, inv, bins[8 * j + 4]);
            bins[8 * j + 5] = fmaf(f2.y, inv, bins[8 * j + 5]);
            bins[8 * j + 6] = fmaf(f3.x, inv, bins[8 * j + 6]);
            bins[8 * j + 7] = fmaf(f3.y, inv, bins[8 * j + 7]);
        }

        // outputs
        const float4 qv = *(const float4*)(embed + (size_t)mi * D + lane * 4);
        *(float4*)(out + (size_t)grow * D + lane * 4) = qv;
        if (lane == 0) out[(size_t)NP * D + grow] = (float)mi;
    }

    // deterministic bin merge: warps (w, w+8) write disjoint cpb arrays per step
    __syncthreads();
    float* cpX = cpb + (wid >> 3) * KC;
    for (int w8 = 0; w8 < 8; w8++) {
        if ((wid & 7) == w8) {
#pragma unroll
            for (int j = 0; j < 8; j++)
#pragma unroll
                for (int q = 0; q < 8; q++)
                    cpX[j * 256 + lane * 8 + q] += bins[8 * j + q];
        }
        __syncthreads();
    }
    for (int i = tid; i < KC; i += 512)
        g_part[(size_t)blockIdx.x * KC + i] = cpb[i] + cpb[KC + i];
}

// ---------------------------------------------------------------------------
// Kernel 4a/4b: two-stage deterministic reduce of partials
// ---------------------------------------------------------------------------
__global__ __launch_bounds__(256) void reduce1_kernel() {
    const int k = blockIdx.x * 256 + threadIdx.x;
    const int b0 = blockIdx.y * 64;
    float s0 = 0.f, s1 = 0.f, s2 = 0.f, s3 = 0.f;
    for (int b = 0; b < 64; b += 4) {
        s0 += g_part[(size_t)(b0 + b + 0) * KC + k];
        s1 += g_part[(size_t)(b0 + b + 1) * KC + k];
        s2 += g_part[(size_t)(b0 + b + 2) * KC + k];
        s3 += g_part[(size_t)(b0 + b + 3) * KC + k];
    }
    g_part2[blockIdx.y * KC + k] = (s0 + s1) + (s2 + s3);
}

__global__ __launch_bounds__(256) void reduce2_kernel() {
    const int k = blockIdx.x * 256 + threadIdx.x;
    float s = 0.f;
#pragma unroll
    for (int b = 0; b < 16; b++) s += g_part2[b * KC + k];
    g_acc[k] = s;
}

// ---------------------------------------------------------------------------
// Kernel 5: diversity loss
// ---------------------------------------------------------------------------
__global__ __launch_bounds__(256) void loss_kernel(float* __restrict__ out) {
    __shared__ float red[8];
    const int tid = threadIdx.x;
    float t = 0.f;
    for (int k = tid; k < KC; k += 256) {
        float p = g_acc[k] * (1.0f / (float)NP);
        t += p * logf(p + LEPS);
    }
#pragma unroll
    for (int off = 16; off > 0; off >>= 1)
        t += __shfl_xor_sync(0xffffffffu, t, off);
    if ((tid & 31) == 0) red[tid >> 5] = t;
    __syncthreads();
    if (tid < 8) {
        t = red[tid];
#pragma unroll
        for (int off = 4; off > 0; off >>= 1)
            t += __shfl_xor_sync(0x000000ffu, t, off);
        if (tid == 0) out[(size_t)NP * D + NP] = t;
    }
}

// ---------------------------------------------------------------------------
extern "C" void kernel_launch(void* const* d_in, const int* in_sizes, int n_in,
                              void* d_out, int out_size) {
    const float* x = (const float*)d_in[0];
    const float* e = (const float*)d_in[1];
    float* out = (float*)d_out;

    cudaFuncSetAttribute(fused_kernel, cudaFuncAttributeMaxDynamicSharedMemorySize,
                         FUSED_SMEM);

    split_kernel<<<((NP + KC) * D + 255) / 256, 256>>>(x, e);
    prep_kernel<<<(KC + 255) / 256, 256>>>(e);
    fused_kernel<<<NP / MB, 512, FUSED_SMEM>>>(x, e, out);
    reduce1_kernel<<<dim3(KC / 256, 16), 256>>>();
    reduce2_kernel<<<KC / 256, 256>>>();
    loss_kernel<<<1, 256>>>(out);
}

// round 15
// speedup vs baseline: 1.0268x; 1.0268x over previous
#include <cuda_runtime.h>
#include <cuda_bf16.h>
#include <cuda_fp16.h>
#include <math_constants.h>
#include <cstdint>

// Problem dims (fixed by setup_inputs)
constexpr int NP = 32768;   // 8*4096 points
constexpr int KC = 2048;    // codebook size
constexpr int D  = 128;     // dim
constexpr float LEPS = 1e-6f;
constexpr float OFFS = 128.0f;
constexpr float SCALE = 1.4426950408889634f / 0.9f;   // log2(e)/T
constexpr float RESCUE_THR_S = 0.5f * SCALE;          // raw 0.5 margin, scaled
constexpr int NT = KC / 128;                          // 16 column tiles

// Scratch (__device__ globals; no allocation allowed)
__device__ __half g_scores16[(size_t)NP * KC];         // 128 MB scaled scores
__device__ float g_esq[KC];                            // ||e_k||^2 (rescue)
__device__ float g_esqc[KC];                           // (OFFS - esq) * SCALE
__device__ __nv_bfloat16 g_Xs[(size_t)NP * 128];       // bf16(x)
__device__ __nv_bfloat16 g_Es[(size_t)KC * 256];       // 2-way bf16 split of embed
__device__ float4 g_ptile[(size_t)NT * NP];            // per-(tile,row) partials: m, s, idx
__device__ float4 g_rowfin[NP];                        // per-row: m, inv, idx
__device__ float g_part[(size_t)(NP / 32) * KC];       // per-block class partials
__device__ float g_part2[16 * KC];
__device__ float g_acc[KC];

// ---------------------------------------------------------------------------
__device__ __forceinline__ uint32_t smem_u32(const void* p) {
    uint32_t a;
    asm("{ .reg .u64 t; cvta.to.shared.u64 t, %1; cvt.u32.u64 %0, t; }" : "=r"(a) : "l"(p));
    return a;
}
__device__ __forceinline__ uint32_t sw128(uint32_t off) { return off ^ ((off >> 3) & 0x70); }
__device__ __forceinline__ float ex2f(float x) {
    float r;
    asm("ex2.approx.f32 %0, %1;" : "=f"(r) : "f"(x));
    return r;
}
__device__ __forceinline__ void cp_async16(uint32_t saddr, const void* gaddr) {
    asm volatile("cp.async.cg.shared.global [%0], [%1], 16;" :: "r"(saddr), "l"(gaddr));
}
#define CP_COMMIT() asm volatile("cp.async.commit_group;" ::: "memory")
#define CP_WAIT(n)  asm volatile("cp.async.wait_group %0;" :: "n"(n) : "memory")

__device__ __forceinline__ void ldm_x4(uint32_t* a, uint32_t addr) {
    asm volatile("ldmatrix.sync.aligned.m8n8.x4.shared.b16 {%0,%1,%2,%3}, [%4];"
                 : "=r"(a[0]), "=r"(a[1]), "=r"(a[2]), "=r"(a[3]) : "r"(addr));
}
__device__ __forceinline__ void mma_bf16(float* c, const uint32_t* a, const uint32_t* b) {
    asm volatile("mma.sync.aligned.m16n8k16.row.col.f32.bf16.bf16.f32 "
                 "{%0,%1,%2,%3}, {%4,%5,%6,%7}, {%8,%9}, {%0,%1,%2,%3};"
                 : "+f"(c[0]), "+f"(c[1]), "+f"(c[2]), "+f"(c[3])
                 : "r"(a[0]), "r"(a[1]), "r"(a[2]), "r"(a[3]), "r"(b[0]), "r"(b[1]));
}

// ---------------------------------------------------------------------------
// Kernel 0: bf16 conversion of x; 2-way bf16 split of embed
// ---------------------------------------------------------------------------
__global__ __launch_bounds__(256) void split_kernel(const float* __restrict__ x,
                                                    const float* __restrict__ e) {
    int i = blockIdx.x * 256 + threadIdx.x;
    if (i < NP * D) {
        g_Xs[i] = __float2bfloat16(x[i]);
    } else {
        int j = i - NP * D;
        if (j >= KC * D) return;
        float v = e[j];
        int c = j & (D - 1);
        __nv_bfloat16* dst = g_Es + (size_t)(j >> 7) * 256;
        __nv_bfloat16 b0 = __float2bfloat16(v);
        float r1 = v - __bfloat162float(b0);
        __nv_bfloat16 b1 = __float2bfloat16(r1);
        dst[c] = b0; dst[128 + c] = b1;
    }
}

// ---------------------------------------------------------------------------
// Kernel 1: e_sq (exact) + scaled epilogue constant
// ---------------------------------------------------------------------------
__global__ void prep_kernel(const float* __restrict__ embed) {
    int k = blockIdx.x * blockDim.x + threadIdx.x;
    if (k < KC) {
        const float4* e = (const float4*)(embed + (size_t)k * D);
        float s = 0.f;
#pragma unroll
        for (int i = 0; i < D / 4; i++) {
            float4 v = e[i];
            s += v.x * v.x + v.y * v.y + v.z * v.z + v.w * v.w;
        }
        g_esq[k] = s;
        g_esqc[k] = (OFFS - s) * SCALE;
    }
}

// ---------------------------------------------------------------------------
// Kernel 2: mma.sync bf16 GEMM; epilogue stores fp16 scaled scores AND
// per-(tile,row) partials (max, argmax, exp-sum) via warp shfl reductions.
// In the final loop, all 32 lanes of a warp cover the SAME row (4 cols each),
// so the per-row tile reduction is a plain full-warp shfl tree.
// ---------------------------------------------------------------------------
constexpr int STG_SZ = 128 * 128;
constexpr int GEMM_SMEM = 3 * 2 * STG_SZ;         // 98304 B

__global__ __launch_bounds__(256, 2) void gemm_kernel() {
    extern __shared__ char smem[];
    const uint32_t sb = smem_u32(smem);
    const int tid = threadIdx.x, wid = tid >> 5, lane = tid & 31;
    const int warp_m = wid & 3, warp_n = wid >> 2;
    const int bm = blockIdx.y * 128, bn = blockIdx.x * 128;

    float acc[2][8][4];
#pragma unroll
    for (int mt = 0; mt < 2; mt++)
#pragma unroll
        for (int nt = 0; nt < 8; nt++)
#pragma unroll
            for (int q = 0; q < 4; q++) acc[mt][nt][q] = 0.f;

    const int lr = tid >> 1;
    const int ls0 = (tid & 1) * 4;

    const int arow = warp_m * 32 + (lane & 7) + ((lane >> 3) & 1) * 8;
    const int acol = ((lane >> 4) & 1) * 16;
    const int b_lrow = ((lane >> 4) & 1) * 8 + (lane & 7);
    const int b_lcol = ((lane >> 3) & 1) * 16;

    auto issue_chunk = [&](int c, int stage) {
        const int p = c >> 1, h = c & 1;
        const uint32_t sa = sb + stage * 2 * STG_SZ;
        const uint32_t sbB = sa + STG_SZ;
        const __nv_bfloat16* ga = g_Xs + (size_t)(bm + lr) * 128 + h * 64;
        const __nv_bfloat16* gb = g_Es + (size_t)(bn + lr) * 256 + p * 128 + h * 64;
#pragma unroll
        for (int s = 0; s < 4; s++) {
            cp_async16(sa + sw128((uint32_t)lr * 128 + (ls0 + s) * 16), ga + (ls0 + s) * 8);
            cp_async16(sbB + sw128((uint32_t)lr * 128 + (ls0 + s) * 16), gb + (ls0 + s) * 8);
        }
        CP_COMMIT();
    };

    issue_chunk(0, 0);
    issue_chunk(1, 1);

#pragma unroll 1
    for (int c = 0; c < 4; c++) {
        const int stage = c % 3;
        if (c < 3) { CP_WAIT(1); } else { CP_WAIT(0); }
        __syncthreads();

        const uint32_t sa = sb + stage * 2 * STG_SZ;
        const uint32_t sbB = sa + STG_SZ;
#pragma unroll
        for (int ks = 0; ks < 4; ks++) {
            uint32_t a[2][4];
#pragma unroll
            for (int mt = 0; mt < 2; mt++)
                ldm_x4(a[mt], sa + sw128((uint32_t)(arow + mt * 16) * 128 + ks * 32 + acol));
#pragma unroll
            for (int ntp = 0; ntp < 4; ntp++) {
                uint32_t b[4];
                ldm_x4(b, sbB + sw128((uint32_t)(warp_n * 64 + ntp * 16 + b_lrow) * 128
                                       + ks * 32 + b_lcol));
                mma_bf16(acc[0][2 * ntp],     a[0], b);
                mma_bf16(acc[1][2 * ntp],     a[1], b);
                mma_bf16(acc[0][2 * ntp + 1], a[0], b + 2);
                mma_bf16(acc[1][2 * ntp + 1], a[1], b + 2);
            }
        }
        if (c <= 1) issue_chunk(c + 2, (c + 2) % 3);
    }
    __syncthreads();

    float* tile = (float*)smem;
#pragma unroll
    for (int mt = 0; mt < 2; mt++) {
        const int r = warp_m * 32 + mt * 16 + (lane >> 2);
#pragma unroll
        for (int nt = 0; nt < 8; nt++) {
            const int cb = warp_n * 64 + nt * 8 + 2 * (lane & 3);
            tile[r * 129 + cb]           = acc[mt][nt][0];
            tile[r * 129 + cb + 1]       = acc[mt][nt][1];
            tile[(r + 8) * 129 + cb]     = acc[mt][nt][2];
            tile[(r + 8) * 129 + cb + 1] = acc[mt][nt][3];
        }
    }
    __syncthreads();

    constexpr float S2 = 2.0f * SCALE;
#pragma unroll
    for (int i = 0; i < 16; i++) {
        const int lin = tid + i * 256;           // 0..4095
        const int row = lin >> 5;                // all lanes of a warp: same row
        const int c4 = (lin & 31) * 4;           // == lane*4
        const float4 ec = *(const float4*)(g_esqc + bn + c4);
        const float sx = fmaf(tile[row * 129 + c4 + 0], S2, ec.x);
        const float sy = fmaf(tile[row * 129 + c4 + 1], S2, ec.y);
        const float sz = fmaf(tile[row * 129 + c4 + 2], S2, ec.z);
        const float sw = fmaf(tile[row * 129 + c4 + 3], S2, ec.w);
        __half2 h0 = __floats2half2_rn(sx, sy);
        __half2 h1 = __floats2half2_rn(sz, sw);
        uint2 u;
        u.x = *(const uint32_t*)&h0;
        u.y = *(const uint32_t*)&h1;
        *(uint2*)(g_scores16 + (size_t)(bm + row) * KC + bn + c4) = u;

        // per-(tile,row) partial: warp max+argmax (tie lowest idx), then exp-sum
        float lm = sx; int li = c4;
        if (sy > lm) { lm = sy; li = c4 + 1; }
        if (sz > lm) { lm = sz; li = c4 + 2; }
        if (sw > lm) { lm = sw; li = c4 + 3; }
#pragma unroll
        for (int off = 16; off > 0; off >>= 1) {
            float om = __shfl_xor_sync(0xffffffffu, lm, off);
            int oi = __shfl_xor_sync(0xffffffffu, li, off);
            if (om > lm || (om == lm && oi < li)) { lm = om; li = oi; }
        }
        float ls = ex2f(sx - lm) + ex2f(sy - lm) + ex2f(sz - lm) + ex2f(sw - lm);
#pragma unroll
        for (int off = 16; off > 0; off >>= 1)
            ls += __shfl_xor_sync(0xffffffffu, ls, off);
        if ((tid & 31) == 0)
            g_ptile[(size_t)blockIdx.x * NP + bm + row] =
                make_float4(lm, ls, __int_as_float(bn + li), 0.f);
    }
}

// ---------------------------------------------------------------------------
// Kernel 2b: finalize per-row header: global max, argmax, inv-sum.
// Deterministic fixed-order combine over the 16 tiles.
// ---------------------------------------------------------------------------
__global__ __launch_bounds__(256) void finalize_kernel() {
    const int r = blockIdx.x * 256 + threadIdx.x;
    float pm[NT], ps[NT];
    float m = -CUDART_INF_F; int mi = 0x7fffffff;
#pragma unroll
    for (int t = 0; t < NT; t++) {
        const float4 p = g_ptile[(size_t)t * NP + r];
        pm[t] = p.x; ps[t] = p.y;
        const int qi = __float_as_int(p.z);
        if (p.x > m || (p.x == m && qi < mi)) { m = p.x; mi = qi; }
    }
    float s = 0.f;
#pragma unroll
    for (int t = 0; t < NT; t++) s += ps[t] * ex2f(pm[t] - m);
    g_rowfin[r] = make_float4(m, 1.f / s, __int_as_float(mi), 0.f);
}

// ---------------------------------------------------------------------------
// Kernel 3: single-pass row kernel. Reads (m, inv, argmax) header; one sweep:
// e = 2^(v-m), bins += e*inv, predicated candidate push; exact fp32 rescue
// when >1 candidate within the margin. No v[64] -> low regs, smem-limited occ.
// ---------------------------------------------------------------------------
__global__ __launch_bounds__(128) void row_kernel(const float* __restrict__ x,
                                                  const float* __restrict__ embed,
                                                  float* __restrict__ out) {
    __shared__ float cp[4][KC];
    __shared__ int s_cnt[4];
    __shared__ int s_list[4][32];
    const int tid = threadIdx.x;
    const int warp = tid >> 5, lane = tid & 31;

    for (int i = tid; i < 4 * KC; i += 128) (&cp[0][0])[i] = 0.f;
    __syncthreads();

    const int row0 = blockIdx.x * 32;
    float* cpw = cp[warp];

    for (int it = 0; it < 8; it++) {
        const int row = row0 + warp * 8 + it;
        const __half* S = g_scores16 + (size_t)row * KC;

        const float4 hd = g_rowfin[row];
        const float m = hd.x, inv = hd.y;
        int mi = __float_as_int(hd.z);
        const float thr = m - RESCUE_THR_S;

        if (lane == 0) s_cnt[warp] = 0;
        __syncwarp();

#pragma unroll
        for (int j = 0; j < 8; j++) {
            const uint4 qq = *(const uint4*)(S + j * 256 + lane * 8);
            const float2 f0 = __half22float2(*(const __half2*)&qq.x);
            const float2 f1 = __half22float2(*(const __half2*)&qq.y);
            const float2 f2 = __half22float2(*(const __half2*)&qq.z);
            const float2 f3 = __half22float2(*(const __half2*)&qq.w);
            float fv[8] = {f0.x, f0.y, f1.x, f1.y, f2.x, f2.y, f3.x, f3.y};
            float ev[8];
#pragma unroll
            for (int q = 0; q < 8; q++) {
                ev[q] = ex2f(fv[q] - m);
                if (fv[q] > thr) {
                    int pos = atomicAdd(&s_cnt[warp], 1);
                    if (pos < 32) s_list[warp][pos] = j * 256 + lane * 8 + q;
                }
            }
            float4* p0 = (float4*)(cpw + j * 256 + lane * 8);
            float4 c0 = p0[0];
            c0.x = fmaf(ev[0], inv, c0.x); c0.y = fmaf(ev[1], inv, c0.y);
            c0.z = fmaf(ev[2], inv, c0.z); c0.w = fmaf(ev[3], inv, c0.w);
            p0[0] = c0;
            float4 c1 = p0[1];
            c1.x = fmaf(ev[4], inv, c1.x); c1.y = fmaf(ev[5], inv, c1.y);
            c1.z = fmaf(ev[6], inv, c1.z); c1.w = fmaf(ev[7], inv, c1.w);
            p0[1] = c1;
        }
        __syncwarp();

        const int cnt = s_cnt[warp];
        if (cnt > 1) {
            const int nc = min(cnt, 32);
            const float4 xa = *(const float4*)(x + (size_t)row * D + lane * 4);
            float bv = -CUDART_INF_F; int bi = 0x7fffffff;
            for (int t = 0; t < nc; t++) {
                const int cidx = s_list[warp][t];
                const float4 ea = *(const float4*)(embed + (size_t)cidx * D + lane * 4);
                float d = xa.x * ea.x + xa.y * ea.y + xa.z * ea.z + xa.w * ea.w;
#pragma unroll
                for (int off = 16; off > 0; off >>= 1)
                    d += __shfl_xor_sync(0xffffffffu, d, off);
                const float sc = 2.f * d - g_esq[cidx];
                if (sc > bv || (sc == bv && cidx < bi)) { bv = sc; bi = cidx; }
            }
            mi = bi;
        }

        const float4 qv = *(const float4*)(embed + (size_t)mi * D + lane * 4);
        *(float4*)(out + (size_t)row * D + lane * 4) = qv;
        if (lane == 0) out[(size_t)NP * D + row] = (float)mi;
    }

    __syncthreads();
    for (int i = tid; i < KC; i += 128)
        g_part[(size_t)blockIdx.x * KC + i] =
            cp[0][i] + cp[1][i] + cp[2][i] + cp[3][i];
}

// ---------------------------------------------------------------------------
// Kernel 4a/4b: two-stage deterministic reduce of partials
// ---------------------------------------------------------------------------
__global__ __launch_bounds__(256) void reduce1_kernel() {
    const int k = blockIdx.x * 256 + threadIdx.x;
    const int b0 = blockIdx.y * 64;
    float s0 = 0.f, s1 = 0.f, s2 = 0.f, s3 = 0.f;
    for (int b = 0; b < 64; b += 4) {
        s0 += g_part[(size_t)(b0 + b + 0) * KC + k];
        s1 += g_part[(size_t)(b0 + b + 1) * KC + k];
        s2 += g_part[(size_t)(b0 + b + 2) * KC + k];
        s3 += g_part[(size_t)(b0 + b + 3) * KC + k];
    }
    g_part2[blockIdx.y * KC + k] = (s0 + s1) + (s2 + s3);
}

__global__ __launch_bounds__(256) void reduce2_kernel() {
    const int k = blockIdx.x * 256 + threadIdx.x;
    float s = 0.f;
#pragma unroll
    for (int b = 0; b < 16; b++) s += g_part2[b * KC + k];
    g_acc[k] = s;
}

// ---------------------------------------------------------------------------
// Kernel 5: diversity loss
// ---------------------------------------------------------------------------
__global__ __launch_bounds__(256) void loss_kernel(float* __restrict__ out) {
    __shared__ float red[8];
    const int tid = threadIdx.x;
    float t = 0.f;
    for (int k = tid; k < KC; k += 256) {
        float p = g_acc[k] * (1.0f / (float)NP);
        t += p * logf(p + LEPS);
    }
#pragma unroll
    for (int off = 16; off > 0; off >>= 1)
        t += __shfl_xor_sync(0xffffffffu, t, off);
    if ((tid & 31) == 0) red[tid >> 5] = t;
    __syncthreads();
    if (tid < 8) {
        t = red[tid];
#pragma unroll
        for (int off = 4; off > 0; off >>= 1)
            t += __shfl_xor_sync(0x000000ffu, t, off);
        if (tid == 0) out[(size_t)NP * D + NP] = t;
    }
}

// ---------------------------------------------------------------------------
extern "C" void kernel_launch(void* const* d_in, const int* in_sizes, int n_in,
                              void* d_out, int out_size) {
    const float* x = (const float*)d_in[0];
    const float* e = (const float*)d_in[1];
    float* out = (float*)d_out;

    cudaFuncSetAttribute(gemm_kernel, cudaFuncAttributeMaxDynamicSharedMemorySize, GEMM_SMEM);

    split_kernel<<<((NP + KC) * D + 255) / 256, 256>>>(x, e);
    prep_kernel<<<(KC + 255) / 256, 256>>>(e);
    gemm_kernel<<<dim3(KC / 128, NP / 128), 256, GEMM_SMEM>>>();
    finalize_kernel<<<NP / 256, 256>>>();
    row_kernel<<<NP / 32, 128>>>(x, e, out);
    reduce1_kernel<<<dim3(KC / 256, 16), 256>>>();
    reduce2_kernel<<<KC / 256, 256>>>();
    loss_kernel<<<1, 256>>>(out);
}

// round 16
// speedup vs baseline: 1.0782x; 1.0500x over previous
#include <cuda_runtime.h>
#include <cuda_bf16.h>
#include <cuda_fp16.h>
#include <math_constants.h>
#include <cstdint>

// Problem dims (fixed by setup_inputs)
constexpr int NP = 32768;   // 8*4096 points
constexpr int KC = 2048;    // codebook size
constexpr int D  = 128;     // dim
constexpr float LEPS = 1e-6f;
constexpr float OFFS = 128.0f;
// Scores stored pre-scaled: S' = (S + OFFS) * SCALE, SCALE = log2(e)/T.
// Softmax prob = 2^(v' - m') (one ex2 per element).
constexpr float SCALE = 1.4426950408889634f / 0.9f;   // 1.60299449
constexpr float RESCUE_THR_S = 0.5f * SCALE;          // raw 0.5 margin, scaled

// Scratch (__device__ globals; no allocation allowed)
__device__ __half g_scores16[(size_t)NP * KC];         // 128 MB score matrix (scaled)
__device__ float g_esq[KC];                            // ||e_k||^2 (exact, for rescue)
__device__ float g_esqc[KC];                           // (OFFS - esq) * SCALE (epilogue)
__device__ __nv_bfloat16 g_Xs[(size_t)NP * 128];       // bf16(x) (8 MB)
__device__ __nv_bfloat16 g_Es[(size_t)KC * 256];       // 2-way bf16 split of embed
__device__ float g_part[(size_t)(NP / 32) * KC];       // per-block class-prob partials
__device__ float g_part2[16 * KC];                     // stage-1 reduced partials
__device__ float g_acc[KC];                            // class sums

// ---------------------------------------------------------------------------
__device__ __forceinline__ uint32_t smem_u32(const void* p) {
    uint32_t a;
    asm("{ .reg .u64 t; cvta.to.shared.u64 t, %1; cvt.u32.u64 %0, t; }" : "=r"(a) : "l"(p));
    return a;
}
__device__ __forceinline__ uint32_t sw128(uint32_t off) { return off ^ ((off >> 3) & 0x70); }
__device__ __forceinline__ float ex2f(float x) {
    float r;
    asm("ex2.approx.f32 %0, %1;" : "=f"(r) : "f"(x));
    return r;
}

__device__ __forceinline__ void cp_async16(uint32_t saddr, const void* gaddr) {
    asm volatile("cp.async.cg.shared.global [%0], [%1], 16;" :: "r"(saddr), "l"(gaddr));
}
#define CP_COMMIT() asm volatile("cp.async.commit_group;" ::: "memory")
#define CP_WAIT(n)  asm volatile("cp.async.wait_group %0;" :: "n"(n) : "memory")

__device__ __forceinline__ void ldm_x4(uint32_t* a, uint32_t addr) {
    asm volatile("ldmatrix.sync.aligned.m8n8.x4.shared.b16 {%0,%1,%2,%3}, [%4];"
                 : "=r"(a[0]), "=r"(a[1]), "=r"(a[2]), "=r"(a[3]) : "r"(addr));
}
__device__ __forceinline__ void mma_bf16(float* c, const uint32_t* a, const uint32_t* b) {
    asm volatile("mma.sync.aligned.m16n8k16.row.col.f32.bf16.bf16.f32 "
                 "{%0,%1,%2,%3}, {%4,%5,%6,%7}, {%8,%9}, {%0,%1,%2,%3};"
                 : "+f"(c[0]), "+f"(c[1]), "+f"(c[2]), "+f"(c[3])
                 : "r"(a[0]), "r"(a[1]), "r"(a[2]), "r"(a[3]), "r"(b[0]), "r"(b[1]));
}

// ---------------------------------------------------------------------------
// Kernel 0: bf16 conversion of x; 2-way bf16 split of embed
// ---------------------------------------------------------------------------
__global__ __launch_bounds__(256) void split_kernel(const float* __restrict__ x,
                                                    const float* __restrict__ e) {
    int i = blockIdx.x * 256 + threadIdx.x;
    if (i < NP * D) {
        g_Xs[i] = __float2bfloat16(x[i]);
    } else {
        int j = i - NP * D;
        if (j >= KC * D) return;
        float v = e[j];
        int c = j & (D - 1);
        __nv_bfloat16* dst = g_Es + (size_t)(j >> 7) * 256;
        __nv_bfloat16 b0 = __float2bfloat16(v);
        float r1 = v - __bfloat162float(b0);
        __nv_bfloat16 b1 = __float2bfloat16(r1);
        dst[c] = b0; dst[128 + c] = b1;
    }
}

// ---------------------------------------------------------------------------
// Kernel 1: e_sq (exact) + scaled epilogue constant
// ---------------------------------------------------------------------------
__global__ void prep_kernel(const float* __restrict__ embed) {
    int k = blockIdx.x * blockDim.x + threadIdx.x;
    if (k < KC) {
        const float4* e = (const float4*)(embed + (size_t)k * D);
        float s = 0.f;
#pragma unroll
        for (int i = 0; i < D / 4; i++) {
            float4 v = e[i];
            s += v.x * v.x + v.y * v.y + v.z * v.z + v.w * v.w;
        }
        g_esq[k] = s;
        g_esqc[k] = (OFFS - s) * SCALE;
    }
}

// ---------------------------------------------------------------------------
// Kernel 2: mma.sync bf16 GEMM  S16 = fp16((2*x0*(e0+e1) - e_sq + OFFS)*SCALE)
// Block 256 thr (8 warps), tile M128 x N128, warp tile 32x64.
// 4 K-chunks of 64 (virtual K=256), 3-stage cp.async, 1 barrier per chunk.
// (Verified R13 code.)
// ---------------------------------------------------------------------------
constexpr int STG_SZ = 128 * 128;                 // 16 KB per operand stage
constexpr int GEMM_SMEM = 3 * 2 * STG_SZ;         // 98304 B (>= 66048 epilogue tile)

__global__ __launch_bounds__(256, 2) void gemm_kernel() {
    extern __shared__ char smem[];
    const uint32_t sb = smem_u32(smem);
    const int tid = threadIdx.x, wid = tid >> 5, lane = tid & 31;
    const int warp_m = wid & 3, warp_n = wid >> 2;
    const int bm = blockIdx.y * 128, bn = blockIdx.x * 128;

    float acc[2][8][4];
#pragma unroll
    for (int mt = 0; mt < 2; mt++)
#pragma unroll
        for (int nt = 0; nt < 8; nt++)
#pragma unroll
            for (int q = 0; q < 4; q++) acc[mt][nt][q] = 0.f;

    const int lr = tid >> 1;                 // rows 0..127 (2 threads/row)
    const int ls0 = (tid & 1) * 4;           // 16B segment base

    const int arow = warp_m * 32 + (lane & 7) + ((lane >> 3) & 1) * 8;
    const int acol = ((lane >> 4) & 1) * 16;
    const int b_lrow = ((lane >> 4) & 1) * 8 + (lane & 7);
    const int b_lcol = ((lane >> 3) & 1) * 16;

    auto issue_chunk = [&](int c, int stage) {
        const int p = c >> 1, h = c & 1;
        const uint32_t sa = sb + stage * 2 * STG_SZ;
        const uint32_t sbB = sa + STG_SZ;
        const __nv_bfloat16* ga = g_Xs + (size_t)(bm + lr) * 128 + h * 64;
        const __nv_bfloat16* gb = g_Es + (size_t)(bn + lr) * 256 + p * 128 + h * 64;
#pragma unroll
        for (int s = 0; s < 4; s++) {
            cp_async16(sa + sw128((uint32_t)lr * 128 + (ls0 + s) * 16), ga + (ls0 + s) * 8);
            cp_async16(sbB + sw128((uint32_t)lr * 128 + (ls0 + s) * 16), gb + (ls0 + s) * 8);
        }
        CP_COMMIT();
    };

    issue_chunk(0, 0);
    issue_chunk(1, 1);

#pragma unroll 1
    for (int c = 0; c < 4; c++) {
        const int stage = c % 3;
        if (c < 3) { CP_WAIT(1); } else { CP_WAIT(0); }
        __syncthreads();

        const uint32_t sa = sb + stage * 2 * STG_SZ;
        const uint32_t sbB = sa + STG_SZ;
#pragma unroll
        for (int ks = 0; ks < 4; ks++) {
            uint32_t a[2][4];
#pragma unroll
            for (int mt = 0; mt < 2; mt++)
                ldm_x4(a[mt], sa + sw128((uint32_t)(arow + mt * 16) * 128 + ks * 32 + acol));
#pragma unroll
            for (int ntp = 0; ntp < 4; ntp++) {
                uint32_t b[4];
                ldm_x4(b, sbB + sw128((uint32_t)(warp_n * 64 + ntp * 16 + b_lrow) * 128
                                       + ks * 32 + b_lcol));
                mma_bf16(acc[0][2 * ntp],     a[0], b);
                mma_bf16(acc[1][2 * ntp],     a[1], b);
                mma_bf16(acc[0][2 * ntp + 1], a[0], b + 2);
                mma_bf16(acc[1][2 * ntp + 1], a[1], b + 2);
            }
        }
        if (c <= 1) issue_chunk(c + 2, (c + 2) % 3);
    }
    __syncthreads();

    // Epilogue: accum -> padded smem tile -> coalesced fp16 scaled scores
    float* tile = (float*)smem;
#pragma unroll
    for (int mt = 0; mt < 2; mt++) {
        const int r = warp_m * 32 + mt * 16 + (lane >> 2);
#pragma unroll
        for (int nt = 0; nt < 8; nt++) {
            const int cb = warp_n * 64 + nt * 8 + 2 * (lane & 3);
            tile[r * 129 + cb]           = acc[mt][nt][0];
            tile[r * 129 + cb + 1]       = acc[mt][nt][1];
            tile[(r + 8) * 129 + cb]     = acc[mt][nt][2];
            tile[(r + 8) * 129 + cb + 1] = acc[mt][nt][3];
        }
    }
    __syncthreads();

    constexpr float S2 = 2.0f * SCALE;
#pragma unroll
    for (int i = 0; i < 16; i++) {
        const int lin = tid + i * 256;           // 0..4095
        const int row = lin >> 5;
        const int c4 = (lin & 31) * 4;
        const float4 ec = *(const float4*)(g_esqc + bn + c4);
        const float sx = fmaf(tile[row * 129 + c4 + 0], S2, ec.x);
        const float sy = fmaf(tile[row * 129 + c4 + 1], S2, ec.y);
        const float sz = fmaf(tile[row * 129 + c4 + 2], S2, ec.z);
        const float sw = fmaf(tile[row * 129 + c4 + 3], S2, ec.w);
        __half2 h0 = __floats2half2_rn(sx, sy);
        __half2 h1 = __floats2half2_rn(sz, sw);
        uint2 u;
        u.x = *(const uint32_t*)&h0;
        u.y = *(const uint32_t*)&h1;
        *(uint2*)(g_scores16 + (size_t)(bm + row) * KC + bn + c4) = u;
    }
}

// ---------------------------------------------------------------------------
// Kernel 3: per-row argmax (+ exact fp32 rescue, scan BEFORE exp) + softmax
// (p = 2^(v'-m')) + class-prob partials + outputs.
// Row values held as __half2 v2[32] (32 regs, not 64) and unpacked transiently
// per use; __launch_bounds__(128, 5) -> <=102 regs -> 20 warps/SM.
// ---------------------------------------------------------------------------
__global__ __launch_bounds__(128, 5) void row_kernel(const float* __restrict__ x,
                                                     const float* __restrict__ embed,
                                                     float* __restrict__ out) {
    __shared__ float cp[4][KC];
    __shared__ int s_cnt[4];
    __shared__ int s_list[4][32];
    const int tid = threadIdx.x;
    const int warp = tid >> 5, lane = tid & 31;

    for (int i = tid; i < 4 * KC; i += 128) (&cp[0][0])[i] = 0.f;
    __syncthreads();

    const int row0 = blockIdx.x * 32;
    float* cpw = cp[warp];

    for (int it = 0; it < 8; it++) {
        const int row = row0 + warp * 8 + it;
        const __half* S = g_scores16 + (size_t)row * KC;

        __half2 v2[32];   // v2[j*4+w] holds cols j*256 + lane*8 + 2w, +1
        float m = -CUDART_INF_F;
        int mi = 0;
#pragma unroll
        for (int j = 0; j < 8; j++) {
            const int kbase = j * 256 + lane * 8;
            const uint4 qq = *(const uint4*)(S + kbase);
            v2[4 * j + 0] = *(const __half2*)&qq.x;
            v2[4 * j + 1] = *(const __half2*)&qq.y;
            v2[4 * j + 2] = *(const __half2*)&qq.z;
            v2[4 * j + 3] = *(const __half2*)&qq.w;
#pragma unroll
            for (int w = 0; w < 4; w++) {
                const float2 f = __half22float2(v2[4 * j + w]);
                if (f.x > m) { m = f.x; mi = kbase + 2 * w; }
                if (f.y > m) { m = f.y; mi = kbase + 2 * w + 1; }
            }
        }
#pragma unroll
        for (int off = 16; off > 0; off >>= 1) {
            float om = __shfl_xor_sync(0xffffffffu, m, off);
            int oi = __shfl_xor_sync(0xffffffffu, mi, off);
            if (om > m || (om == m && oi < mi)) { m = om; mi = oi; }
        }

        // Candidate detection for exact rescue (on raw scaled scores).
        const float thr = m - RESCUE_THR_S;
        int cnt = 0;
#pragma unroll
        for (int i = 0; i < 32; i++) {
            const float2 f = __half22float2(v2[i]);
            cnt += (f.x > thr) ? 1 : 0;
            cnt += (f.y > thr) ? 1 : 0;
        }
#pragma unroll
        for (int off = 16; off > 0; off >>= 1)
            cnt += __shfl_xor_sync(0xffffffffu, cnt, off);

        if (cnt > 1) {
            if (lane == 0) s_cnt[warp] = 0;
            __syncwarp();
#pragma unroll
            for (int i = 0; i < 32; i++) {
                const float2 f = __half22float2(v2[i]);
                const int kidx = (i >> 2) * 256 + lane * 8 + 2 * (i & 3);
                if (f.x > thr) {
                    int pos = atomicAdd(&s_cnt[warp], 1);
                    if (pos < 32) s_list[warp][pos] = kidx;
                }
                if (f.y > thr) {
                    int pos = atomicAdd(&s_cnt[warp], 1);
                    if (pos < 32) s_list[warp][pos] = kidx + 1;
                }
            }
            __syncwarp();
            const int nc = min(s_cnt[warp], 32);
            const float4 xa = *(const float4*)(x + (size_t)row * D + lane * 4);
            float bv = -CUDART_INF_F; int bi = 0x7fffffff;
            for (int t = 0; t < nc; t++) {
                const int cidx = s_list[warp][t];
                const float4 ea = *(const float4*)(embed + (size_t)cidx * D + lane * 4);
                float d = xa.x * ea.x + xa.y * ea.y + xa.z * ea.z + xa.w * ea.w;
#pragma unroll
                for (int off = 16; off > 0; off >>= 1)
                    d += __shfl_xor_sync(0xffffffffu, d, off);
                const float sc = 2.f * d - g_esq[cidx];
                if (sc > bv || (sc == bv && cidx < bi)) { bv = sc; bi = cidx; }
            }
            mi = bi;
        }

        // softmax: p = 2^(v - m); exps re-packed to half2 (s uses fp32 exps)
        float s = 0.f;
#pragma unroll
        for (int i = 0; i < 32; i++) {
            const float2 f = __half22float2(v2[i]);
            const float e0 = ex2f(f.x - m);
            const float e1 = ex2f(f.y - m);
            s += e0 + e1;
            v2[i] = __floats2half2_rn(e0, e1);
        }
#pragma unroll
        for (int off = 16; off > 0; off >>= 1)
            s += __shfl_xor_sync(0xffffffffu, s, off);
        const float inv = 1.f / s;

#pragma unroll
        for (int j = 0; j < 8; j++) {
            const float2 f0 = __half22float2(v2[4 * j + 0]);
            const float2 f1 = __half22float2(v2[4 * j + 1]);
            const float2 f2 = __half22float2(v2[4 * j + 2]);
            const float2 f3 = __half22float2(v2[4 * j + 3]);
            float4* p0 = (float4*)(cpw + j * 256 + lane * 8);
            float4 c0 = p0[0];
            c0.x = fmaf(f0.x, inv, c0.x); c0.y = fmaf(f0.y, inv, c0.y);
            c0.z = fmaf(f1.x, inv, c0.z); c0.w = fmaf(f1.y, inv, c0.w);
            p0[0] = c0;
            float4 c1 = p0[1];
            c1.x = fmaf(f2.x, inv, c1.x); c1.y = fmaf(f2.y, inv, c1.y);
            c1.z = fmaf(f3.x, inv, c1.z); c1.w = fmaf(f3.y, inv, c1.w);
            p0[1] = c1;
        }

        const float4 qv = *(const float4*)(embed + (size_t)mi * D + lane * 4);
        *(float4*)(out + (size_t)row * D + lane * 4) = qv;
        if (lane == 0) out[(size_t)NP * D + row] = (float)mi;
    }

    __syncthreads();
    for (int i = tid; i < KC; i += 128)
        g_part[(size_t)blockIdx.x * KC + i] =
            cp[0][i] + cp[1][i] + cp[2][i] + cp[3][i];
}

// ---------------------------------------------------------------------------
// Kernel 4a/4b: two-stage deterministic reduce of partials
// ---------------------------------------------------------------------------
__global__ __launch_bounds__(256) void reduce1_kernel() {
    const int k = blockIdx.x * 256 + threadIdx.x;
    const int b0 = blockIdx.y * 64;
    float s0 = 0.f, s1 = 0.f, s2 = 0.f, s3 = 0.f;
    for (int b = 0; b < 64; b += 4) {
        s0 += g_part[(size_t)(b0 + b + 0) * KC + k];
        s1 += g_part[(size_t)(b0 + b + 1) * KC + k];
        s2 += g_part[(size_t)(b0 + b + 2) * KC + k];
        s3 += g_part[(size_t)(b0 + b + 3) * KC + k];
    }
    g_part2[blockIdx.y * KC + k] = (s0 + s1) + (s2 + s3);
}

__global__ __launch_bounds__(256) void reduce2_kernel() {
    const int k = blockIdx.x * 256 + threadIdx.x;
    float s = 0.f;
#pragma unroll
    for (int b = 0; b < 16; b++) s += g_part2[b * KC + k];
    g_acc[k] = s;
}

// ---------------------------------------------------------------------------
// Kernel 5: diversity loss
// ---------------------------------------------------------------------------
__global__ __launch_bounds__(256) void loss_kernel(float* __restrict__ out) {
    __shared__ float red[8];
    const int tid = threadIdx.x;
    float t = 0.f;
    for (int k = tid; k < KC; k += 256) {
        float p = g_acc[k] * (1.0f / (float)NP);
        t += p * logf(p + LEPS);
    }
#pragma unroll
    for (int off = 16; off > 0; off >>= 1)
        t += __shfl_xor_sync(0xffffffffu, t, off);
    if ((tid & 31) == 0) red[tid >> 5] = t;
    __syncthreads();
    if (tid < 8) {
        t = red[tid];
#pragma unroll
        for (int off = 4; off > 0; off >>= 1)
            t += __shfl_xor_sync(0x000000ffu, t, off);
        if (tid == 0) out[(size_t)NP * D + NP] = t;
    }
}

// ---------------------------------------------------------------------------
extern "C" void kernel_launch(void* const* d_in, const int* in_sizes, int n_in,
                              void* d_out, int out_size) {
    const float* x = (const float*)d_in[0];
    const float* e = (const float*)d_in[1];
    float* out = (float*)d_out;

    cudaFuncSetAttribute(gemm_kernel, cudaFuncAttributeMaxDynamicSharedMemorySize, GEMM_SMEM);

    split_kernel<<<((NP + KC) * D + 255) / 256, 256>>>(x, e);
    prep_kernel<<<(KC + 255) / 256, 256>>>(e);
    gemm_kernel<<<dim3(KC / 128, NP / 128), 256, GEMM_SMEM>>>();
    row_kernel<<<NP / 32, 128>>>(x, e, out);
    reduce1_kernel<<<dim3(KC / 256, 16), 256>>>();
    reduce2_kernel<<<KC / 256, 256>>>();
    loss_kernel<<<1, 256>>>(out);
}

// round 17
// speedup vs baseline: 1.1355x; 1.0532x over previous
#include <cuda_runtime.h>
#include <cuda_bf16.h>
#include <cuda_fp16.h>
#include <math_constants.h>
#include <cstdint>

// Problem dims (fixed by setup_inputs)
constexpr int NP = 32768;   // 8*4096 points
constexpr int KC = 2048;    // codebook size
constexpr int D  = 128;     // dim
constexpr float TEMP_INV = 1.0f / 0.9f;
constexpr float LEPS = 1e-6f;
constexpr float RESCUE_THR = 0.5f;    // covers split (0.125) + fp16 quant (0.125) stack
constexpr float OFFS = 128.0f;        // recenters S ~ -128+-28 to ~0 for fp16 storage

// Scratch (__device__ globals; no allocation allowed)
__device__ __half g_scores16[(size_t)NP * KC];         // 128 MB score matrix (S + OFFS)
__device__ float g_esq[KC];                            // ||e_k||^2
__device__ __nv_bfloat16 g_Xs[(size_t)NP * 128];       // bf16(x) (8 MB)
__device__ __nv_bfloat16 g_Es[(size_t)KC * 256];       // 2-way bf16 split of embed
__device__ float g_part[(size_t)(NP / 32) * KC];       // per-block class-prob partials
__device__ float g_part2[64 * KC];                     // stage-1 reduced partials (512 KB)
__device__ float g_acc[KC];                            // class sums

// ---------------------------------------------------------------------------
__device__ __forceinline__ uint32_t smem_u32(const void* p) {
    uint32_t a;
    asm("{ .reg .u64 t; cvta.to.shared.u64 t, %1; cvt.u32.u64 %0, t; }" : "=r"(a) : "l"(p));
    return a;
}
__device__ __forceinline__ uint32_t sw128(uint32_t off) { return off ^ ((off >> 3) & 0x70); }

__device__ __forceinline__ void cp_async16(uint32_t saddr, const void* gaddr) {
    asm volatile("cp.async.cg.shared.global [%0], [%1], 16;" :: "r"(saddr), "l"(gaddr));
}
#define CP_COMMIT() asm volatile("cp.async.commit_group;" ::: "memory")
#define CP_WAIT(n)  asm volatile("cp.async.wait_group %0;" :: "n"(n) : "memory")

__device__ __forceinline__ void ldm_x4(uint32_t* a, uint32_t addr) {
    asm volatile("ldmatrix.sync.aligned.m8n8.x4.shared.b16 {%0,%1,%2,%3}, [%4];"
                 : "=r"(a[0]), "=r"(a[1]), "=r"(a[2]), "=r"(a[3]) : "r"(addr));
}
__device__ __forceinline__ void mma_bf16(float* c, const uint32_t* a, const uint32_t* b) {
    asm volatile("mma.sync.aligned.m16n8k16.row.col.f32.bf16.bf16.f32 "
                 "{%0,%1,%2,%3}, {%4,%5,%6,%7}, {%8,%9}, {%0,%1,%2,%3};"
                 : "+f"(c[0]), "+f"(c[1]), "+f"(c[2]), "+f"(c[3])
                 : "r"(a[0]), "r"(a[1]), "r"(a[2]), "r"(a[3]), "r"(b[0]), "r"(b[1]));
}

// ---------------------------------------------------------------------------
// Kernel 0 (merged): bf16 conversion of x; 2-way bf16 split of embed; e_sq.
// First SPLIT_BLOCKS blocks do the elementwise work; the trailing 8 blocks
// compute the per-code ||e||^2 (disjoint outputs, no interaction).
// ---------------------------------------------------------------------------
constexpr int SPLIT_BLOCKS = (NP + KC) * D / 256;   // 17408

__global__ __launch_bounds__(256) void split_prep_kernel(const float* __restrict__ x,
                                                         const float* __restrict__ e) {
    if (blockIdx.x < SPLIT_BLOCKS) {
        int i = blockIdx.x * 256 + threadIdx.x;
        if (i < NP * D) {
            g_Xs[i] = __float2bfloat16(x[i]);
        } else {
            int j = i - NP * D;
            float v = e[j];
            int c = j & (D - 1);
            __nv_bfloat16* dst = g_Es + (size_t)(j >> 7) * 256;
            __nv_bfloat16 b0 = __float2bfloat16(v);
            float r1 = v - __bfloat162float(b0);
            __nv_bfloat16 b1 = __float2bfloat16(r1);
            dst[c] = b0; dst[128 + c] = b1;
        }
    } else {
        int k = (blockIdx.x - SPLIT_BLOCKS) * 256 + threadIdx.x;
        if (k < KC) {
            const float4* ep = (const float4*)(e + (size_t)k * D);
            float s = 0.f;
#pragma unroll
            for (int i = 0; i < D / 4; i++) {
                float4 v = ep[i];
                s += v.x * v.x + v.y * v.y + v.z * v.z + v.w * v.w;
            }
            g_esq[k] = s;
        }
    }
}

// ---------------------------------------------------------------------------
// Kernel 2: mma.sync bf16 GEMM  S16 = fp16(2*(x0*e0 + x0*e1) - e_sq + OFFS)
// Block 256 thr (8 warps), tile M128 x N128, warp tile 32x64.
// 4 K-chunks of 64 (virtual K=256), 3-stage cp.async, 1 barrier per chunk.
// (Byte-identical to the verified R10 272.9us kernel.)
// ---------------------------------------------------------------------------
constexpr int STG_SZ = 128 * 128;                 // 16 KB per operand stage
constexpr int GEMM_SMEM = 3 * 2 * STG_SZ;         // 98304 B (>= 66048 epilogue tile)

__global__ __launch_bounds__(256, 2) void gemm_kernel() {
    extern __shared__ char smem[];
    const uint32_t sb = smem_u32(smem);
    const int tid = threadIdx.x, wid = tid >> 5, lane = tid & 31;
    const int warp_m = wid & 3, warp_n = wid >> 2;
    const int bm = blockIdx.y * 128, bn = blockIdx.x * 128;

    float acc[2][8][4];
#pragma unroll
    for (int mt = 0; mt < 2; mt++)
#pragma unroll
        for (int nt = 0; nt < 8; nt++)
#pragma unroll
            for (int q = 0; q < 4; q++) acc[mt][nt][q] = 0.f;

    const int lr = tid >> 1;                 // rows 0..127 (2 threads/row)
    const int ls0 = (tid & 1) * 4;           // 16B segment base

    // A x4: 16 rows x 32B
    const int arow = warp_m * 32 + (lane & 7) + ((lane >> 3) & 1) * 8;
    const int acol = ((lane >> 4) & 1) * 16;
    // B x4 (two paired 8-row n-tiles)
    const int b_lrow = ((lane >> 4) & 1) * 8 + (lane & 7);
    const int b_lcol = ((lane >> 3) & 1) * 16;

    // chunk c: p = c>>1 selects e0/e1, h = c&1 selects 64-dim half.
    auto issue_chunk = [&](int c, int stage) {
        const int p = c >> 1, h = c & 1;
        const uint32_t sa = sb + stage * 2 * STG_SZ;
        const uint32_t sbB = sa + STG_SZ;
        const __nv_bfloat16* ga = g_Xs + (size_t)(bm + lr) * 128 + h * 64;
        const __nv_bfloat16* gb = g_Es + (size_t)(bn + lr) * 256 + p * 128 + h * 64;
#pragma unroll
        for (int s = 0; s < 4; s++) {
            cp_async16(sa + sw128((uint32_t)lr * 128 + (ls0 + s) * 16), ga + (ls0 + s) * 8);
            cp_async16(sbB + sw128((uint32_t)lr * 128 + (ls0 + s) * 16), gb + (ls0 + s) * 8);
        }
        CP_COMMIT();
    };

    issue_chunk(0, 0);
    issue_chunk(1, 1);

#pragma unroll 1
    for (int c = 0; c < 4; c++) {
        const int stage = c % 3;
        if (c < 3) { CP_WAIT(1); } else { CP_WAIT(0); }
        __syncthreads();

        const uint32_t sa = sb + stage * 2 * STG_SZ;
        const uint32_t sbB = sa + STG_SZ;
#pragma unroll
        for (int ks = 0; ks < 4; ks++) {
            uint32_t a[2][4];
#pragma unroll
            for (int mt = 0; mt < 2; mt++)
                ldm_x4(a[mt], sa + sw128((uint32_t)(arow + mt * 16) * 128 + ks * 32 + acol));
#pragma unroll
            for (int ntp = 0; ntp < 4; ntp++) {
                uint32_t b[4];
                ldm_x4(b, sbB + sw128((uint32_t)(warp_n * 64 + ntp * 16 + b_lrow) * 128
                                       + ks * 32 + b_lcol));
                mma_bf16(acc[0][2 * ntp],     a[0], b);
                mma_bf16(acc[1][2 * ntp],     a[1], b);
                mma_bf16(acc[0][2 * ntp + 1], a[0], b + 2);
                mma_bf16(acc[1][2 * ntp + 1], a[1], b + 2);
            }
        }
        if (c <= 1) issue_chunk(c + 2, (c + 2) % 3);
    }
    __syncthreads();

    // Epilogue: accum -> padded smem tile -> coalesced fp16 (2*s - esq + OFFS)
    float* tile = (float*)smem;
#pragma unroll
    for (int mt = 0; mt < 2; mt++) {
        const int r = warp_m * 32 + mt * 16 + (lane >> 2);
#pragma unroll
        for (int nt = 0; nt < 8; nt++) {
            const int cb = warp_n * 64 + nt * 8 + 2 * (lane & 3);
            tile[r * 129 + cb]           = acc[mt][nt][0];
            tile[r * 129 + cb + 1]       = acc[mt][nt][1];
            tile[(r + 8) * 129 + cb]     = acc[mt][nt][2];
            tile[(r + 8) * 129 + cb + 1] = acc[mt][nt][3];
        }
    }
    __syncthreads();

#pragma unroll
    for (int i = 0; i < 16; i++) {
        const int lin = tid + i * 256;           // 0..4095
        const int row = lin >> 5;
        const int c4 = (lin & 31) * 4;
        const float4 esq = *(const float4*)(g_esq + bn + c4);
        const float sx = 2.f * tile[row * 129 + c4 + 0] - esq.x + OFFS;
        const float sy = 2.f * tile[row * 129 + c4 + 1] - esq.y + OFFS;
        const float sz = 2.f * tile[row * 129 + c4 + 2] - esq.z + OFFS;
        const float sw = 2.f * tile[row * 129 + c4 + 3] - esq.w + OFFS;
        __half2 h0 = __floats2half2_rn(sx, sy);
        __half2 h1 = __floats2half2_rn(sz, sw);
        uint2 u;
        u.x = *(const uint32_t*)&h0;
        u.y = *(const uint32_t*)&h1;
        *(uint2*)(g_scores16 + (size_t)(bm + row) * KC + bn + c4) = u;
    }
}

// ---------------------------------------------------------------------------
// Kernel 3: per-row argmax (+ exact fp32 rescue) + softmax + class-prob
// partials + outputs. (Byte-identical to the verified R10 272.9us kernel.)
// ---------------------------------------------------------------------------
__global__ __launch_bounds__(128) void row_kernel(const float* __restrict__ x,
                                                  const float* __restrict__ embed,
                                                  float* __restrict__ out) {
    __shared__ float cp[4][KC];
    __shared__ int s_cnt[4];
    __shared__ int s_list[4][32];
    const int tid = threadIdx.x;
    const int warp = tid >> 5, lane = tid & 31;

    for (int i = tid; i < 4 * KC; i += 128) (&cp[0][0])[i] = 0.f;
    __syncthreads();

    const int row0 = blockIdx.x * 32;
    float* cpw = cp[warp];

    for (int it = 0; it < 8; it++) {
        const int row = row0 + warp * 8 + it;
        const __half* S = g_scores16 + (size_t)row * KC;

        float v[64];
        float m = -CUDART_INF_F;
        int mi = 0;
#pragma unroll
        for (int j = 0; j < 8; j++) {
            const int kbase = j * 256 + lane * 8;
            const uint4 qq = *(const uint4*)(S + kbase);
            const float2 f0 = __half22float2(*(const __half2*)&qq.x);
            const float2 f1 = __half22float2(*(const __half2*)&qq.y);
            const float2 f2 = __half22float2(*(const __half2*)&qq.z);
            const float2 f3 = __half22float2(*(const __half2*)&qq.w);
            v[8 * j + 0] = f0.x; v[8 * j + 1] = f0.y;
            v[8 * j + 2] = f1.x; v[8 * j + 3] = f1.y;
            v[8 * j + 4] = f2.x; v[8 * j + 5] = f2.y;
            v[8 * j + 6] = f3.x; v[8 * j + 7] = f3.y;
#pragma unroll
            for (int q = 0; q < 8; q++)
                if (v[8 * j + q] > m) { m = v[8 * j + q]; mi = kbase + q; }
        }
#pragma unroll
        for (int off = 16; off > 0; off >>= 1) {
            float om = __shfl_xor_sync(0xffffffffu, m, off);
            int oi = __shfl_xor_sync(0xffffffffu, mi, off);
            if (om > m || (om == m && oi < mi)) { m = om; mi = oi; }
        }

        // Candidate detection for exact rescue (before v[] is overwritten).
        const float thr = m - RESCUE_THR;
        int cnt = 0;
#pragma unroll
        for (int j = 0; j < 64; j++) cnt += (v[j] > thr) ? 1 : 0;
#pragma unroll
        for (int off = 16; off > 0; off >>= 1)
            cnt += __shfl_xor_sync(0xffffffffu, cnt, off);

        if (cnt > 1) {
            if (lane == 0) s_cnt[warp] = 0;
            __syncwarp();
#pragma unroll
            for (int j = 0; j < 64; j++) {
                if (v[j] > thr) {
                    int pos = atomicAdd(&s_cnt[warp], 1);
                    if (pos < 32)
                        s_list[warp][pos] = (j >> 3) * 256 + lane * 8 + (j & 7);
                }
            }
            __syncwarp();
            const int nc = min(s_cnt[warp], 32);
            const float4 xa = *(const float4*)(x + (size_t)row * D + lane * 4);
            float bv = -CUDART_INF_F; int bi = 0x7fffffff;
            for (int t = 0; t < nc; t++) {
                const int cidx = s_list[warp][t];
                const float4 ea = *(const float4*)(embed + (size_t)cidx * D + lane * 4);
                float d = xa.x * ea.x + xa.y * ea.y + xa.z * ea.z + xa.w * ea.w;
#pragma unroll
                for (int off = 16; off > 0; off >>= 1)
                    d += __shfl_xor_sync(0xffffffffu, d, off);
                const float sc = 2.f * d - g_esq[cidx];
                if (sc > bv || (sc == bv && cidx < bi)) { bv = sc; bi = cidx; }
            }
            mi = bi;
        }

        // softmax (approx scores — fine for the loss; OFFS cancels in v - m)
        float s = 0.f;
#pragma unroll
        for (int j = 0; j < 64; j++) {
            float e = __expf((v[j] - m) * TEMP_INV);
            v[j] = e;
            s += e;
        }
#pragma unroll
        for (int off = 16; off > 0; off >>= 1)
            s += __shfl_xor_sync(0xffffffffu, s, off);
        const float inv = 1.f / s;

#pragma unroll
        for (int j = 0; j < 8; j++) {
            float4* p0 = (float4*)(cpw + j * 256 + lane * 8);
            float4 c0 = p0[0];
            c0.x += v[8 * j + 0] * inv; c0.y += v[8 * j + 1] * inv;
            c0.z += v[8 * j + 2] * inv; c0.w += v[8 * j + 3] * inv;
            p0[0] = c0;
            float4 c1 = p0[1];
            c1.x += v[8 * j + 4] * inv; c1.y += v[8 * j + 5] * inv;
            c1.z += v[8 * j + 6] * inv; c1.w += v[8 * j + 7] * inv;
            p0[1] = c1;
        }

        float4 q = *(const float4*)(embed + (size_t)mi * D + lane * 4);
        *(float4*)(out + (size_t)row * D + lane * 4) = q;
        if (lane == 0) out[(size_t)NP * D + row] = (float)mi;
    }

    __syncthreads();
    for (int i = tid; i < KC; i += 128)
        g_part[(size_t)blockIdx.x * KC + i] =
            cp[0][i] + cp[1][i] + cp[2][i] + cp[3][i];
}

// ---------------------------------------------------------------------------
// Kernel 4a/4b: two-stage deterministic reduce of partials.
// Stage 1 widened to grid (8, 64): 16 partials per block (8x the TLP of the
// old (8,16)x64 shape -> latency-bound 8MB read finishes ~3x faster).
// ---------------------------------------------------------------------------
__global__ __launch_bounds__(256) void reduce1_kernel() {
    const int k = blockIdx.x * 256 + threadIdx.x;
    const int b0 = blockIdx.y * 16;
    float s0 = 0.f, s1 = 0.f, s2 = 0.f, s3 = 0.f;
#pragma unroll
    for (int b = 0; b < 16; b += 4) {
        s0 += g_part[(size_t)(b0 + b + 0) * KC + k];
        s1 += g_part[(size_t)(b0 + b + 1) * KC + k];
        s2 += g_part[(size_t)(b0 + b + 2) * KC + k];
        s3 += g_part[(size_t)(b0 + b + 3) * KC + k];
    }
    g_part2[blockIdx.y * KC + k] = (s0 + s1) + (s2 + s3);
}

__global__ __launch_bounds__(256) void reduce2_kernel() {
    const int k = blockIdx.x * 256 + threadIdx.x;
    float s0 = 0.f, s1 = 0.f, s2 = 0.f, s3 = 0.f;
#pragma unroll
    for (int b = 0; b < 64; b += 4) {
        s0 += g_part2[(b + 0) * KC + k];
        s1 += g_part2[(b + 1) * KC + k];
        s2 += g_part2[(b + 2) * KC + k];
        s3 += g_part2[(b + 3) * KC + k];
    }
    g_acc[k] = (s0 + s1) + (s2 + s3);
}

// ---------------------------------------------------------------------------
// Kernel 5: diversity loss
// ---------------------------------------------------------------------------
__global__ __launch_bounds__(256) void loss_kernel(float* __restrict__ out) {
    __shared__ float red[8];
    const int tid = threadIdx.x;
    float t = 0.f;
    for (int k = tid; k < KC; k += 256) {
        float p = g_acc[k] * (1.0f / (float)NP);
        t += p * logf(p + LEPS);
    }
#pragma unroll
    for (int off = 16; off > 0; off >>= 1)
        t += __shfl_xor_sync(0xffffffffu, t, off);
    if ((tid & 31) == 0) red[tid >> 5] = t;
    __syncthreads();
    if (tid < 8) {
        t = red[tid];
#pragma unroll
        for (int off = 4; off > 0; off >>= 1)
            t += __shfl_xor_sync(0x000000ffu, t, off);
        if (tid == 0) out[(size_t)NP * D + NP] = t;
    }
}

// ---------------------------------------------------------------------------
extern "C" void kernel_launch(void* const* d_in, const int* in_sizes, int n_in,
                              void* d_out, int out_size) {
    const float* x = (const float*)d_in[0];
    const float* e = (const float*)d_in[1];
    float* out = (float*)d_out;

    cudaFuncSetAttribute(gemm_kernel, cudaFuncAttributeMaxDynamicSharedMemorySize, GEMM_SMEM);

    split_prep_kernel<<<SPLIT_BLOCKS + KC / 256, 256>>>(x, e);
    gemm_kernel<<<dim3(KC / 128, NP / 128), 256, GEMM_SMEM>>>();
    row_kernel<<<NP / 32, 128>>>(x, e, out);
    reduce1_kernel<<<dim3(KC / 256, 64), 256>>>();
    reduce2_kernel<<<KC / 256, 256>>>();
    loss_kernel<<<1, 256>>>(out);
}